// round 1
// baseline (speedup 1.0000x reference)
#include <cuda_runtime.h>
#include <cuda_fp16.h>

#define B_ 512
#define T_ 365
#define D_ 16
#define S_ 32
#define H_ 256

// ---------------- device scratch (no dynamic allocation allowed) ----------------
// Packed recurrent weights: index (k2*256 + j) -> uint4 holding 4 gates (i,f,g,o),
// each uint = half2(W[gate*256+j][2*k2], W[gate*256+j][2*k2+1])
__device__ uint4  g_Whh0p[128 * 256];
__device__ uint4  g_Wih1p[128 * 256];
__device__ uint4  g_Whh1p[128 * 256];
// Layer-0 input weights, fp32, transposed: index (k*256 + j) -> float4 over gates
__device__ float4 g_Wih0t[16 * 256];
// Fused biases per hidden unit j: float4 over gates
__device__ float4 g_b0v[256];
__device__ float4 g_b1v[256];
// Initial hidden/cell state from static projection: [b][j]
__device__ float  g_h0[B_ * H_];

// ---------------- preprocessing kernels ----------------
__global__ void k_pack(const float* __restrict__ W, int which) {
    // W is [1024, 256] row-major (PyTorch [4H, H]); pack to fp16 pairs along K.
    uint4* dst = (which == 0) ? g_Whh0p : (which == 1) ? g_Wih1p : g_Whh1p;
    int e = blockIdx.x * blockDim.x + threadIdx.x;   // e = k2*256 + j, e < 32768
    if (e >= 128 * 256) return;
    int k2 = e >> 8;
    int j  = e & 255;
    uint4 v;
#pragma unroll
    for (int g = 0; g < 4; g++) {
        float a = W[(g * H_ + j) * 256 + 2 * k2];
        float b = W[(g * H_ + j) * 256 + 2 * k2 + 1];
        __half2 h = __floats2half2_rn(a, b);
        ((unsigned*)&v)[g] = *reinterpret_cast<unsigned*>(&h);
    }
    dst[e] = v;
}

__global__ void k_wih0t(const float* __restrict__ W) {
    // W is [1024, 16]; transpose to [(k*256+j)] float4 over gates, keep fp32.
    int e = blockIdx.x * blockDim.x + threadIdx.x;   // e = k*256 + j, e < 4096
    if (e >= 16 * 256) return;
    int k = e >> 8;
    int j = e & 255;
    float4 v;
#pragma unroll
    for (int g = 0; g < 4; g++)
        ((float*)&v)[g] = W[(g * H_ + j) * D_ + k];
    g_Wih0t[e] = v;
}

__global__ void k_bias(const float* __restrict__ bih0, const float* __restrict__ bhh0,
                       const float* __restrict__ bih1, const float* __restrict__ bhh1) {
    int j = blockIdx.x * blockDim.x + threadIdx.x;
    if (j >= H_) return;
    float4 v0, v1;
#pragma unroll
    for (int g = 0; g < 4; g++) {
        ((float*)&v0)[g] = bih0[g * H_ + j] + bhh0[g * H_ + j];
        ((float*)&v1)[g] = bih1[g * H_ + j] + bhh1[g * H_ + j];
    }
    g_b0v[j] = v0;
    g_b1v[j] = v1;
}

__global__ void k_h0(const float* __restrict__ xst, const float* __restrict__ Ws,
                     const float* __restrict__ bs) {
    int e = blockIdx.x * blockDim.x + threadIdx.x;   // e = b*256 + j
    if (e >= B_ * H_) return;
    int b = e >> 8;
    int j = e & 255;
    float s = bs[j];
#pragma unroll
    for (int k = 0; k < S_; k++)
        s += xst[b * S_ + k] * Ws[j * S_ + k];
    g_h0[e] = s;
}

// ---------------- main persistent LSTM kernel ----------------
union U64F2 { unsigned long long u; float2 f; };

__device__ __forceinline__ void fma2(unsigned long long& d, unsigned long long a,
                                     unsigned long long b) {
    asm("fma.rn.f32x2 %0, %1, %2, %0;" : "+l"(d) : "l"(a), "l"(b));
}
__device__ __forceinline__ unsigned long long f2u(float2 v) { U64F2 t; t.f = v; return t.u; }
__device__ __forceinline__ float2 u2f(unsigned long long v) { U64F2 t; t.u = v; return t.f; }
__device__ __forceinline__ float sigm(float v) { return 1.0f / (1.0f + __expf(-v)); }

__global__ void __launch_bounds__(256, 1)
lstm_main(const float* __restrict__ x, const float* __restrict__ Wo,
          const float* __restrict__ bo, float* __restrict__ out) {
    __shared__ float h0s[4][H_];
    __shared__ float h1s[4][H_];
    __shared__ float xs[4][D_];
    __shared__ float Wos[H_];

    const int j = threadIdx.x;
    const int rowBase = blockIdx.x * 4;
    const int warp = j >> 5, lane = j & 31;

    const float4 b0v = g_b0v[j];
    const float4 b1v = g_b1v[j];

    float c0[4], c1[4];
#pragma unroll
    for (int r = 0; r < 4; r++) {
        float hv = g_h0[(rowBase + r) * H_ + j];
        h0s[r][j] = hv;
        h1s[r][j] = hv;
        c0[r] = hv;
        c1[r] = hv;
    }
    Wos[j] = Wo[j];
    const float bo0 = __ldg(bo);
    __syncthreads();

    for (int t = 0; t < T_; t++) {
        // stage x_t for this CTA's 4 rows
        if (j < 64) {
            int r = j >> 4, d = j & 15;
            xs[r][d] = x[((rowBase + r) * T_ + t) * D_ + d];
        }
        __syncthreads();

        // ================= layer 0 =================
        float accS[4][4];   // [gate][row] fp32 scalar part (bias + x@Wih0^T)
#pragma unroll
        for (int g = 0; g < 4; g++)
#pragma unroll
            for (int r = 0; r < 4; r++)
                accS[g][r] = ((const float*)&b0v)[g];

#pragma unroll
        for (int k = 0; k < D_; k++) {
            float4 w = g_Wih0t[k * 256 + j];
            const float* wa = (const float*)&w;
#pragma unroll
            for (int r = 0; r < 4; r++) {
                float xv = xs[r][k];
                accS[0][r] += wa[0] * xv;
                accS[1][r] += wa[1] * xv;
                accS[2][r] += wa[2] * xv;
                accS[3][r] += wa[3] * xv;
            }
        }

        unsigned long long acc2[4][4];  // [gate][row], f32x2 lanes = (even-k, odd-k) partials
#pragma unroll
        for (int g = 0; g < 4; g++)
#pragma unroll
            for (int r = 0; r < 4; r++)
                acc2[g][r] = 0ull;

#pragma unroll 4
        for (int k2 = 0; k2 < 128; k2++) {
            uint4 wp = g_Whh0p[k2 * 256 + j];
            unsigned long long wg[4];
#pragma unroll
            for (int g = 0; g < 4; g++) {
                unsigned wv = ((const unsigned*)&wp)[g];
                __half2 hh = *reinterpret_cast<__half2*>(&wv);
                wg[g] = f2u(__half22float2(hh));
            }
#pragma unroll
            for (int r = 0; r < 4; r++) {
                unsigned long long hv =
                    *reinterpret_cast<const unsigned long long*>(&h0s[r][2 * k2]);
                fma2(acc2[0][r], wg[0], hv);
                fma2(acc2[1][r], wg[1], hv);
                fma2(acc2[2][r], wg[2], hv);
                fma2(acc2[3][r], wg[3], hv);
            }
        }

        float hn[4];
#pragma unroll
        for (int r = 0; r < 4; r++) {
            float2 vi = u2f(acc2[0][r]), vf = u2f(acc2[1][r]);
            float2 vg = u2f(acc2[2][r]), vo = u2f(acc2[3][r]);
            float gi = accS[0][r] + vi.x + vi.y;
            float gf = accS[1][r] + vf.x + vf.y;
            float gg = accS[2][r] + vg.x + vg.y;
            float go = accS[3][r] + vo.x + vo.y;
            float iv = sigm(gi), fv = sigm(gf), gv = tanhf(gg), ov = sigm(go);
            c0[r] = fv * c0[r] + iv * gv;
            hn[r] = ov * tanhf(c0[r]);
        }
        __syncthreads();   // all reads of old h0s complete
#pragma unroll
        for (int r = 0; r < 4; r++) h0s[r][j] = hn[r];
        __syncthreads();

        // ================= layer 1 =================
#pragma unroll
        for (int g = 0; g < 4; g++)
#pragma unroll
            for (int r = 0; r < 4; r++)
                acc2[g][r] = 0ull;

#pragma unroll 4
        for (int k2 = 0; k2 < 128; k2++) {     // input part: Wih1 @ h0_new
            uint4 wp = g_Wih1p[k2 * 256 + j];
            unsigned long long wg[4];
#pragma unroll
            for (int g = 0; g < 4; g++) {
                unsigned wv = ((const unsigned*)&wp)[g];
                __half2 hh = *reinterpret_cast<__half2*>(&wv);
                wg[g] = f2u(__half22float2(hh));
            }
#pragma unroll
            for (int r = 0; r < 4; r++) {
                unsigned long long hv =
                    *reinterpret_cast<const unsigned long long*>(&h0s[r][2 * k2]);
                fma2(acc2[0][r], wg[0], hv);
                fma2(acc2[1][r], wg[1], hv);
                fma2(acc2[2][r], wg[2], hv);
                fma2(acc2[3][r], wg[3], hv);
            }
        }
#pragma unroll 4
        for (int k2 = 0; k2 < 128; k2++) {     // recurrent part: Whh1 @ h1
            uint4 wp = g_Whh1p[k2 * 256 + j];
            unsigned long long wg[4];
#pragma unroll
            for (int g = 0; g < 4; g++) {
                unsigned wv = ((const unsigned*)&wp)[g];
                __half2 hh = *reinterpret_cast<__half2*>(&wv);
                wg[g] = f2u(__half22float2(hh));
            }
#pragma unroll
            for (int r = 0; r < 4; r++) {
                unsigned long long hv =
                    *reinterpret_cast<const unsigned long long*>(&h1s[r][2 * k2]);
                fma2(acc2[0][r], wg[0], hv);
                fma2(acc2[1][r], wg[1], hv);
                fma2(acc2[2][r], wg[2], hv);
                fma2(acc2[3][r], wg[3], hv);
            }
        }
#pragma unroll
        for (int r = 0; r < 4; r++) {
            float2 vi = u2f(acc2[0][r]), vf = u2f(acc2[1][r]);
            float2 vg = u2f(acc2[2][r]), vo = u2f(acc2[3][r]);
            float gi = ((const float*)&b1v)[0] + vi.x + vi.y;
            float gf = ((const float*)&b1v)[1] + vf.x + vf.y;
            float gg = ((const float*)&b1v)[2] + vg.x + vg.y;
            float go = ((const float*)&b1v)[3] + vo.x + vo.y;
            float iv = sigm(gi), fv = sigm(gf), gv = tanhf(gg), ov = sigm(go);
            c1[r] = fv * c1[r] + iv * gv;
            hn[r] = ov * tanhf(c1[r]);
        }
        __syncthreads();
#pragma unroll
        for (int r = 0; r < 4; r++) h1s[r][j] = hn[r];
        __syncthreads();

        // ================= output head: out[b,t] = h1 . Wo + bo =================
        if (warp < 4) {
            float s = 0.0f;
#pragma unroll
            for (int m = 0; m < 8; m++) {
                int jj = lane + m * 32;
                s += h1s[warp][jj] * Wos[jj];
            }
#pragma unroll
            for (int off = 16; off; off >>= 1)
                s += __shfl_down_sync(0xffffffffu, s, off);
            if (lane == 0)
                out[(rowBase + warp) * T_ + t] = s + bo0;
        }
        // next iteration's first __syncthreads orders h1s reads vs future writes
    }
}

// ---------------- launch ----------------
extern "C" void kernel_launch(void* const* d_in, const int* in_sizes, int n_in,
                              void* d_out, int out_size) {
    const float* x     = (const float*)d_in[0];
    const float* xst   = (const float*)d_in[1];
    const float* Wih0  = (const float*)d_in[2];
    const float* Whh0  = (const float*)d_in[3];
    const float* bih0  = (const float*)d_in[4];
    const float* bhh0  = (const float*)d_in[5];
    const float* Wih1  = (const float*)d_in[6];
    const float* Whh1  = (const float*)d_in[7];
    const float* bih1  = (const float*)d_in[8];
    const float* bhh1  = (const float*)d_in[9];
    const float* Ws    = (const float*)d_in[10];
    const float* bs    = (const float*)d_in[11];
    const float* Wo    = (const float*)d_in[12];
    const float* bo    = (const float*)d_in[13];
    float* out = (float*)d_out;

    k_pack<<<128, 256>>>(Whh0, 0);
    k_pack<<<128, 256>>>(Wih1, 1);
    k_pack<<<128, 256>>>(Whh1, 2);
    k_wih0t<<<16, 256>>>(Wih0);
    k_bias<<<1, 256>>>(bih0, bhh0, bih1, bhh1);
    k_h0<<<512, 256>>>(xst, Ws, bs);
    lstm_main<<<128, 256>>>(x, Wo, bo, out);
}